// round 7
// baseline (speedup 1.0000x reference)
#include <cuda_runtime.h>
#include <cuda_bf16.h>
#include <cstdint>

#define NN 50000
#define EE 800000
#define LN_EPS 1e-5f
#define ST 36

// ===================== static scratch =====================
__device__ int   g_deg[NN];
__device__ int   g_rowptr[NN + 1];
__device__ int   g_cursor[NN];
__device__ int   g_csrsrc[EE];
__device__ float g_invdeg[NN];
__device__ float g_agg0[(size_t)NN * 64];
__device__ float g_m0[(size_t)NN * 256];   // merged h0 (mu | v)
__device__ float g_a1[(size_t)NN * 256];   // merged agg(h0)
__device__ float g_m1[(size_t)NN * 256];   // merged h1
__device__ float g_a2[(size_t)NN * 256];   // merged agg(h1)

struct MArgs {
    const float *Agg, *Hin, *Wl, *Wr, *bl;
    float* out;
    int ldA, ldH, ldO;
};

__device__ __forceinline__ float to_tf32(float x) {
    uint32_t u;
    asm("cvt.rna.tf32.f32 %0, %1;" : "=r"(u) : "f"(x));
    return __uint_as_float(u);
}

__device__ __forceinline__ void mma_tf32(float& d0, float& d1, float& d2, float& d3,
                                         uint32_t a0, uint32_t a1, uint32_t a2, uint32_t a3,
                                         uint32_t b0, uint32_t b1) {
    asm volatile(
        "mma.sync.aligned.m16n8k8.row.col.f32.tf32.tf32.f32 "
        "{%0,%1,%2,%3}, {%4,%5,%6,%7}, {%8,%9}, {%0,%1,%2,%3};"
        : "+f"(d0), "+f"(d1), "+f"(d2), "+f"(d3)
        : "r"(a0), "r"(a1), "r"(a2), "r"(a3), "r"(b0), "r"(b1));
}

// ===================== CSR build =====================
__global__ void k_count(const int* __restrict__ dst, int* __restrict__ deg) {
    int e = blockIdx.x * blockDim.x + threadIdx.x;
    if (e < EE) atomicAdd(&deg[dst[e]], 1);
}

__global__ void k_scan(const int* __restrict__ deg, int* __restrict__ rowptr,
                       int* __restrict__ cursor, float* __restrict__ invdeg) {
    __shared__ int sums[1024];
    const int t = threadIdx.x;
    const int CH = (NN + 1023) / 1024;
    int s = 0;
    #pragma unroll 4
    for (int i = 0; i < CH; ++i) {
        int idx = t * CH + i;
        if (idx < NN) s += deg[idx];
    }
    sums[t] = s;
    __syncthreads();
    for (int off = 1; off < 1024; off <<= 1) {
        int v = 0;
        if (t >= off) v = sums[t - off];
        __syncthreads();
        if (t >= off) sums[t] += v;
        __syncthreads();
    }
    int run = (t == 0) ? 0 : sums[t - 1];
    for (int i = 0; i < CH; ++i) {
        int idx = t * CH + i;
        if (idx < NN) {
            int d = deg[idx];
            rowptr[idx] = run;
            cursor[idx] = run;
            invdeg[idx] = 1.0f / (float)(d > 0 ? d : 1);
            run += d;
        }
    }
    if (t == 1023) rowptr[NN] = run;
}

__global__ void k_scatter(const int* __restrict__ src, const int* __restrict__ dst,
                          int* __restrict__ cursor, int* __restrict__ csrsrc) {
    int e = blockIdx.x * blockDim.x + threadIdx.x;
    if (e < EE) {
        int pos = atomicAdd(&cursor[dst[e]], 1);
        csrsrc[pos] = src[e];
    }
}

// ===================== gathers =====================
// 64-wide (input features), 2-way unroll (round-3 form)
__global__ void k_gather64(const float* __restrict__ h, float* __restrict__ out,
                           const int* __restrict__ rowptr, const int* __restrict__ csrsrc,
                           const float* __restrict__ invdeg) {
    int gw   = (blockIdx.x * blockDim.x + threadIdx.x) >> 5;
    int lane = threadIdx.x & 31;
    if (gw >= NN) return;
    int s = rowptr[gw], e = rowptr[gw + 1];
    float2 a0 = make_float2(0, 0), a1 = make_float2(0, 0);
    int j = s;
    for (; j + 1 < e; j += 2) {
        int s0 = csrsrc[j], s1 = csrsrc[j + 1];
        float2 v0 = *(const float2*)(h + (size_t)s0 * 64 + lane * 2);
        float2 v1 = *(const float2*)(h + (size_t)s1 * 64 + lane * 2);
        a0.x += v0.x; a0.y += v0.y;
        a1.x += v1.x; a1.y += v1.y;
    }
    if (j < e) {
        int s0 = csrsrc[j];
        float2 v0 = *(const float2*)(h + (size_t)s0 * 64 + lane * 2);
        a0.x += v0.x; a0.y += v0.y;
    }
    float iv = invdeg[gw];
    float2 r;
    r.x = (a0.x + a1.x) * iv; r.y = (a0.y + a1.y) * iv;
    *(float2*)(out + (size_t)gw * 64 + lane * 2) = r;
}

// 256-wide merged rows (both towers in one pass), 2-way edge unroll
// lane covers cols [lane*4, lane*4+4) and [128 + lane*4, ...): 4 LDG.128 in flight
__global__ void k_gather256(const float* __restrict__ h, float* __restrict__ out,
                            const int* __restrict__ rowptr, const int* __restrict__ csrsrc,
                            const float* __restrict__ invdeg) {
    int gw   = (blockIdx.x * blockDim.x + threadIdx.x) >> 5;
    int lane = threadIdx.x & 31;
    if (gw >= NN) return;
    int s = rowptr[gw], e = rowptr[gw + 1];
    float4 a0 = make_float4(0, 0, 0, 0), b0 = make_float4(0, 0, 0, 0);
    float4 a1 = make_float4(0, 0, 0, 0), b1 = make_float4(0, 0, 0, 0);
    int j = s;
    for (; j + 1 < e; j += 2) {
        const float* r0 = h + (size_t)csrsrc[j] * 256;
        const float* r1 = h + (size_t)csrsrc[j + 1] * 256;
        float4 v0 = *(const float4*)(r0 + lane * 4);
        float4 w0 = *(const float4*)(r0 + 128 + lane * 4);
        float4 v1 = *(const float4*)(r1 + lane * 4);
        float4 w1 = *(const float4*)(r1 + 128 + lane * 4);
        a0.x += v0.x; a0.y += v0.y; a0.z += v0.z; a0.w += v0.w;
        b0.x += w0.x; b0.y += w0.y; b0.z += w0.z; b0.w += w0.w;
        a1.x += v1.x; a1.y += v1.y; a1.z += v1.z; a1.w += v1.w;
        b1.x += w1.x; b1.y += w1.y; b1.z += w1.z; b1.w += w1.w;
    }
    if (j < e) {
        const float* r0 = h + (size_t)csrsrc[j] * 256;
        float4 v0 = *(const float4*)(r0 + lane * 4);
        float4 w0 = *(const float4*)(r0 + 128 + lane * 4);
        a0.x += v0.x; a0.y += v0.y; a0.z += v0.z; a0.w += v0.w;
        b0.x += w0.x; b0.y += w0.y; b0.z += w0.z; b0.w += w0.w;
    }
    float iv = invdeg[gw];
    float4 r;
    r.x = (a0.x + a1.x) * iv; r.y = (a0.y + a1.y) * iv;
    r.z = (a0.z + a1.z) * iv; r.w = (a0.w + a1.w) * iv;
    *(float4*)(out + (size_t)gw * 256 + lane * 4) = r;
    r.x = (b0.x + b1.x) * iv; r.y = (b0.y + b1.y) * iv;
    r.z = (b0.z + b1.z) * iv; r.w = (b0.w + b1.w) * iv;
    *(float4*)(out + (size_t)gw * 256 + 128 + lane * 4) = r;
}

// ===================== tf32 mma dense (round-3 tiling, runtime strides) ==========
// out[m, col] = [Agg(m) | Hin(m)] @ [Wl | Wr]^T + bl ; dual tower via blockIdx.y
template <int DI, int DO>
__global__ __launch_bounds__(256) void k_mma(MArgs pa, MArgs pb) {
    constexpr int WN = DO / 2;
    constexpr int NI = WN / 8;

    const MArgs P = blockIdx.y ? pb : pa;

    __shared__ float As[128 * ST];
    __shared__ float Ws[DO * ST];

    const int tid    = threadIdx.x;
    const int wid    = tid >> 5;
    const int lane   = tid & 31;
    const int g      = lane >> 2;
    const int tig    = lane & 3;
    const int warp_m = wid >> 1;
    const int warp_n = wid & 1;
    const int bm     = blockIdx.x * 128;

    float acc[2][NI][4];
    #pragma unroll
    for (int mi = 0; mi < 2; ++mi)
        #pragma unroll
        for (int ni = 0; ni < NI; ++ni)
            #pragma unroll
            for (int q = 0; q < 4; ++q) acc[mi][ni][q] = 0.f;

    #pragma unroll
    for (int ph = 0; ph < 2; ++ph) {
        const float* __restrict__ Asrc = ph ? P.Hin : P.Agg;
        const float* __restrict__ Wsrc = ph ? P.Wr : P.Wl;
        const int lda = ph ? P.ldH : P.ldA;
        #pragma unroll
        for (int c = 0; c < DI / 32; ++c) {
            const int kl = c * 32;
            #pragma unroll
            for (int i = 0; i < 4; ++i) {
                int flat = tid + i * 256;
                int row = flat >> 3, q = flat & 7;
                int m = bm + row;
                float4 v = make_float4(0.f, 0.f, 0.f, 0.f);
                if (m < NN) v = *(const float4*)(Asrc + (size_t)m * lda + kl + q * 4);
                v.x = to_tf32(v.x); v.y = to_tf32(v.y); v.z = to_tf32(v.z); v.w = to_tf32(v.w);
                *(float4*)(As + row * ST + q * 4) = v;
            }
            #pragma unroll
            for (int i = 0; i < DO / 32; ++i) {
                int flat = tid + i * 256;
                int row = flat >> 3, q = flat & 7;
                float4 v = *(const float4*)(Wsrc + (size_t)row * DI + kl + q * 4);
                v.x = to_tf32(v.x); v.y = to_tf32(v.y); v.z = to_tf32(v.z); v.w = to_tf32(v.w);
                *(float4*)(Ws + row * ST + q * 4) = v;
            }
            __syncthreads();

            #pragma unroll
            for (int kk = 0; kk < 4; ++kk) {
                const int kb = kk * 8;
                uint32_t a[2][4];
                #pragma unroll
                for (int mi = 0; mi < 2; ++mi) {
                    int rb = warp_m * 32 + mi * 16;
                    a[mi][0] = __float_as_uint(As[(rb + g) * ST + kb + tig]);
                    a[mi][1] = __float_as_uint(As[(rb + g + 8) * ST + kb + tig]);
                    a[mi][2] = __float_as_uint(As[(rb + g) * ST + kb + tig + 4]);
                    a[mi][3] = __float_as_uint(As[(rb + g + 8) * ST + kb + tig + 4]);
                }
                #pragma unroll
                for (int ni = 0; ni < NI; ++ni) {
                    int nb = warp_n * WN + ni * 8;
                    uint32_t b0 = __float_as_uint(Ws[(nb + g) * ST + kb + tig]);
                    uint32_t b1 = __float_as_uint(Ws[(nb + g) * ST + kb + tig + 4]);
                    #pragma unroll
                    for (int mi = 0; mi < 2; ++mi)
                        mma_tf32(acc[mi][ni][0], acc[mi][ni][1], acc[mi][ni][2], acc[mi][ni][3],
                                 a[mi][0], a[mi][1], a[mi][2], a[mi][3], b0, b1);
                }
            }
            __syncthreads();
        }
    }

    #pragma unroll
    for (int ni = 0; ni < NI; ++ni) {
        int col = warp_n * WN + ni * 8 + tig * 2;
        float b0 = P.bl[col], b1 = P.bl[col + 1];
        #pragma unroll
        for (int mi = 0; mi < 2; ++mi) {
            int r0 = bm + warp_m * 32 + mi * 16 + g;
            if (r0 < NN)
                *(float2*)(P.out + (size_t)r0 * P.ldO + col) =
                    make_float2(acc[mi][ni][0] + b0, acc[mi][ni][1] + b1);
            int r1 = r0 + 8;
            if (r1 < NN)
                *(float2*)(P.out + (size_t)r1 * P.ldO + col) =
                    make_float2(acc[mi][ni][2] + b0, acc[mi][ni][3] + b1);
        }
    }
}

// ===================== LayerNorm + ReLU on merged [N,256] buffer ==========
// blockIdx.y selects tower half (cols t*128..t*128+128) and its g/b.
__global__ void k_lnrelu2(float* __restrict__ h,
                          const float* __restrict__ gA, const float* __restrict__ bA,
                          const float* __restrict__ gB, const float* __restrict__ bB) {
    const float* __restrict__ g = blockIdx.y ? gB : gA;
    const float* __restrict__ b = blockIdx.y ? bB : bA;
    int n    = (blockIdx.x * blockDim.x + threadIdx.x) >> 5;
    int lane = threadIdx.x & 31;
    if (n >= NN) return;
    float* row = h + (size_t)n * 256 + blockIdx.y * 128;
    float4 v = *(const float4*)(row + lane * 4);
    float s = v.x + v.y + v.z + v.w;
    #pragma unroll
    for (int off = 16; off > 0; off >>= 1) s += __shfl_xor_sync(0xFFFFFFFF, s, off);
    float mean = s * (1.0f / 128.0f);
    float dx = v.x - mean, dy = v.y - mean, dz = v.z - mean, dw = v.w - mean;
    float sq = dx * dx + dy * dy + dz * dz + dw * dw;
    #pragma unroll
    for (int off = 16; off > 0; off >>= 1) sq += __shfl_xor_sync(0xFFFFFFFF, sq, off);
    float rs = rsqrtf(sq * (1.0f / 128.0f) + LN_EPS);
    float4 gg = *(const float4*)(g + lane * 4);
    float4 bb = *(const float4*)(b + lane * 4);
    float4 r;
    r.x = fmaxf(dx * rs * gg.x + bb.x, 0.f);
    r.y = fmaxf(dy * rs * gg.y + bb.y, 0.f);
    r.z = fmaxf(dz * rs * gg.z + bb.z, 0.f);
    r.w = fmaxf(dw * rs * gg.w + bb.w, 0.f);
    *(float4*)(row + lane * 4) = r;
}

// ===================== host =====================
extern "C" void kernel_launch(void* const* d_in, const int* in_sizes, int n_in,
                              void* d_out, int out_size) {
    const float* x   = (const float*)d_in[0];
    const int*   ei  = (const int*)d_in[1];
    const int*   src = ei;
    const int*   dst = ei + EE;

    int *pDeg, *pRow, *pCur, *pCsr;
    float *pInv, *pAgg0, *pM0, *pA1, *pM1, *pA2;
    cudaGetSymbolAddress((void**)&pDeg, g_deg);
    cudaGetSymbolAddress((void**)&pRow, g_rowptr);
    cudaGetSymbolAddress((void**)&pCur, g_cursor);
    cudaGetSymbolAddress((void**)&pCsr, g_csrsrc);
    cudaGetSymbolAddress((void**)&pInv, g_invdeg);
    cudaGetSymbolAddress((void**)&pAgg0, g_agg0);
    cudaGetSymbolAddress((void**)&pM0, g_m0);
    cudaGetSymbolAddress((void**)&pA1, g_a1);
    cudaGetSymbolAddress((void**)&pM1, g_m1);
    cudaGetSymbolAddress((void**)&pA2, g_a2);

    const float* W[2][13];
    for (int t = 0; t < 2; ++t)
        for (int i = 0; i < 13; ++i) W[t][i] = (const float*)d_in[2 + t * 13 + i];
    // 0 Wl0, 1 bl0, 2 Wr0, 3 g0, 4 b0, 5 Wl1, 6 bl1, 7 Wr1, 8 g1, 9 b1, 10 Wl2, 11 bl2, 12 Wr2

    const int EB = (EE + 255) / 256;
    const int GW = (NN * 32 + 255) / 256;
    const int DB = (NN + 127) / 128;

    cudaMemsetAsync(pDeg, 0, NN * sizeof(int), 0);
    k_count<<<EB, 256>>>(dst, pDeg);
    k_scan<<<1, 1024>>>(pDeg, pRow, pCur, pInv);
    k_scatter<<<EB, 256>>>(src, dst, pCur, pCsr);

    // shared input aggregation (64-wide)
    k_gather64<<<GW, 256>>>(x, pAgg0, pRow, pCsr, pInv);

    MArgs a, b;
    // ---- layer 0: [agg0 | x] -> merged h0 ----
    a = {pAgg0, x, W[0][0], W[0][2], W[0][1], pM0,       64, 64, 256};
    b = {pAgg0, x, W[1][0], W[1][2], W[1][1], pM0 + 128, 64, 64, 256};
    k_mma<64, 128><<<dim3(DB, 2), 256>>>(a, b);
    k_lnrelu2<<<dim3(GW, 2), 256>>>(pM0, W[0][3], W[0][4], W[1][3], W[1][4]);

    // ---- layer 1: merged gather, per-tower GEMM into merged h1 ----
    k_gather256<<<GW, 256>>>(pM0, pA1, pRow, pCsr, pInv);
    a = {pA1,       pM0,       W[0][5], W[0][7], W[0][6], pM1,       256, 256, 256};
    b = {pA1 + 128, pM0 + 128, W[1][5], W[1][7], W[1][6], pM1 + 128, 256, 256, 256};
    k_mma<128, 128><<<dim3(DB, 2), 256>>>(a, b);
    k_lnrelu2<<<dim3(GW, 2), 256>>>(pM1, W[0][8], W[0][9], W[1][8], W[1][9]);

    // ---- layer 2: merged gather, per-tower GEMM into d_out ----
    k_gather256<<<GW, 256>>>(pM1, pA2, pRow, pCsr, pInv);
    float* outT0 = (float*)d_out;
    float* outT1 = (float*)d_out + (size_t)NN * 64;
    a = {pA2,       pM1,       W[0][10], W[0][12], W[0][11], outT0, 256, 256, 64};
    b = {pA2 + 128, pM1 + 128, W[1][10], W[1][12], W[1][11], outT1, 256, 256, 64};
    k_mma<128, 64><<<dim3(DB, 2), 256>>>(a, b);
}

// round 8
// speedup vs baseline: 1.1408x; 1.1408x over previous
#include <cuda_runtime.h>
#include <cuda_bf16.h>
#include <cstdint>

#define NN 50000
#define EE 800000
#define LN_EPS 1e-5f
#define ST 36

// ===================== static scratch =====================
__device__ int   g_deg[NN];
__device__ int   g_rowptr[NN + 1];
__device__ int   g_cursor[NN];
__device__ int   g_csrsrc[EE];
__device__ float g_invdeg[NN];
__device__ float g_agg0[(size_t)NN * 64];
__device__ float g_bufA[(size_t)NN * 128];          // h0 (fp32)
__device__ float g_bufB[(size_t)NN * 128];          // agg scratch
__device__ float g_bufC[(size_t)NN * 128];          // h1 (fp32)
__device__ __nv_bfloat16 g_hbf[(size_t)NN * 128];   // bf16 copy of h for gathering

__device__ __forceinline__ float to_tf32(float x) {
    uint32_t u;
    asm("cvt.rna.tf32.f32 %0, %1;" : "=r"(u) : "f"(x));
    return __uint_as_float(u);
}

__device__ __forceinline__ void mma_tf32(float& d0, float& d1, float& d2, float& d3,
                                         uint32_t a0, uint32_t a1, uint32_t a2, uint32_t a3,
                                         uint32_t b0, uint32_t b1) {
    asm volatile(
        "mma.sync.aligned.m16n8k8.row.col.f32.tf32.tf32.f32 "
        "{%0,%1,%2,%3}, {%4,%5,%6,%7}, {%8,%9}, {%0,%1,%2,%3};"
        : "+f"(d0), "+f"(d1), "+f"(d2), "+f"(d3)
        : "r"(a0), "r"(a1), "r"(a2), "r"(a3), "r"(b0), "r"(b1));
}

// ===================== CSR build =====================
__global__ void k_count(const int* __restrict__ dst, int* __restrict__ deg) {
    int e = blockIdx.x * blockDim.x + threadIdx.x;
    if (e < EE) atomicAdd(&deg[dst[e]], 1);
}

// scan + cursor init + invdeg (fused)
__global__ void k_scan(const int* __restrict__ deg, int* __restrict__ rowptr,
                       int* __restrict__ cursor, float* __restrict__ invdeg) {
    __shared__ int sums[1024];
    const int t = threadIdx.x;
    const int CH = (NN + 1023) / 1024;
    int s = 0;
    #pragma unroll 4
    for (int i = 0; i < CH; ++i) {
        int idx = t * CH + i;
        if (idx < NN) s += deg[idx];
    }
    sums[t] = s;
    __syncthreads();
    for (int off = 1; off < 1024; off <<= 1) {
        int v = 0;
        if (t >= off) v = sums[t - off];
        __syncthreads();
        if (t >= off) sums[t] += v;
        __syncthreads();
    }
    int run = (t == 0) ? 0 : sums[t - 1];
    for (int i = 0; i < CH; ++i) {
        int idx = t * CH + i;
        if (idx < NN) {
            int d = deg[idx];
            rowptr[idx] = run;
            cursor[idx] = run;
            invdeg[idx] = 1.0f / (float)(d > 0 ? d : 1);
            run += d;
        }
    }
    if (t == 1023) rowptr[NN] = run;
}

__global__ void k_scatter(const int* __restrict__ src, const int* __restrict__ dst,
                          int* __restrict__ cursor, int* __restrict__ csrsrc) {
    int e = blockIdx.x * blockDim.x + threadIdx.x;
    if (e < EE) {
        int pos = atomicAdd(&cursor[dst[e]], 1);
        csrsrc[pos] = src[e];
    }
}

// ===================== gathers =====================
// input features (fp32, 64-wide), 2-way unroll — round-3 form
__global__ void k_gather64(const float* __restrict__ h, float* __restrict__ out,
                           const int* __restrict__ rowptr, const int* __restrict__ csrsrc,
                           const float* __restrict__ invdeg) {
    int gw   = (blockIdx.x * blockDim.x + threadIdx.x) >> 5;
    int lane = threadIdx.x & 31;
    if (gw >= NN) return;
    int s = rowptr[gw], e = rowptr[gw + 1];
    float2 a0 = make_float2(0, 0), a1 = make_float2(0, 0);
    int j = s;
    for (; j + 1 < e; j += 2) {
        int s0 = csrsrc[j], s1 = csrsrc[j + 1];
        float2 v0 = *(const float2*)(h + (size_t)s0 * 64 + lane * 2);
        float2 v1 = *(const float2*)(h + (size_t)s1 * 64 + lane * 2);
        a0.x += v0.x; a0.y += v0.y;
        a1.x += v1.x; a1.y += v1.y;
    }
    if (j < e) {
        int s0 = csrsrc[j];
        float2 v0 = *(const float2*)(h + (size_t)s0 * 64 + lane * 2);
        a0.x += v0.x; a0.y += v0.y;
    }
    float iv = invdeg[gw];
    float2 r;
    r.x = (a0.x + a1.x) * iv; r.y = (a0.y + a1.y) * iv;
    *(float2*)(out + (size_t)gw * 64 + lane * 2) = r;
}

// hidden state gather: reads bf16 rows (256B/row), accumulates fp32, writes fp32
__global__ void k_gather128bf(const __nv_bfloat16* __restrict__ hb, float* __restrict__ out,
                              const int* __restrict__ rowptr, const int* __restrict__ csrsrc,
                              const float* __restrict__ invdeg) {
    int gw   = (blockIdx.x * blockDim.x + threadIdx.x) >> 5;
    int lane = threadIdx.x & 31;
    if (gw >= NN) return;
    int s = rowptr[gw], e = rowptr[gw + 1];
    float4 a0 = make_float4(0, 0, 0, 0), a1 = make_float4(0, 0, 0, 0);
    int j = s;
    for (; j + 1 < e; j += 2) {
        int s0 = csrsrc[j], s1 = csrsrc[j + 1];
        uint2 u0 = *(const uint2*)(hb + (size_t)s0 * 128 + lane * 4);
        uint2 u1 = *(const uint2*)(hb + (size_t)s1 * 128 + lane * 4);
        float2 f0 = __bfloat1622float2(*reinterpret_cast<const __nv_bfloat162*>(&u0.x));
        float2 f1 = __bfloat1622float2(*reinterpret_cast<const __nv_bfloat162*>(&u0.y));
        float2 f2 = __bfloat1622float2(*reinterpret_cast<const __nv_bfloat162*>(&u1.x));
        float2 f3 = __bfloat1622float2(*reinterpret_cast<const __nv_bfloat162*>(&u1.y));
        a0.x += f0.x; a0.y += f0.y; a0.z += f1.x; a0.w += f1.y;
        a1.x += f2.x; a1.y += f2.y; a1.z += f3.x; a1.w += f3.y;
    }
    if (j < e) {
        int s0 = csrsrc[j];
        uint2 u0 = *(const uint2*)(hb + (size_t)s0 * 128 + lane * 4);
        float2 f0 = __bfloat1622float2(*reinterpret_cast<const __nv_bfloat162*>(&u0.x));
        float2 f1 = __bfloat1622float2(*reinterpret_cast<const __nv_bfloat162*>(&u0.y));
        a0.x += f0.x; a0.y += f0.y; a0.z += f1.x; a0.w += f1.y;
    }
    float iv = invdeg[gw];
    float4 r;
    r.x = (a0.x + a1.x) * iv; r.y = (a0.y + a1.y) * iv;
    r.z = (a0.z + a1.z) * iv; r.w = (a0.w + a1.w) * iv;
    *(float4*)(out + (size_t)gw * 128 + lane * 4) = r;
}

// ===================== tf32 mma dense (round-3 tiling, compile-time strides) =====
// out = [Agg|Hin]@[Wl|Wr]^T + bl. 8 warps 4x2; warp tile 32x64.
template <int DI, int DO>
__global__ __launch_bounds__(256) void k_mma(
    const float* __restrict__ Agg, const float* __restrict__ Hin,
    const float* __restrict__ Wl, const float* __restrict__ Wr,
    const float* __restrict__ bl, float* __restrict__ out) {
    constexpr int WN = DO / 2;
    constexpr int NI = WN / 8;

    __shared__ float As[128 * ST];
    __shared__ float Ws[DO * ST];

    const int tid    = threadIdx.x;
    const int wid    = tid >> 5;
    const int lane   = tid & 31;
    const int g      = lane >> 2;
    const int tig    = lane & 3;
    const int warp_m = wid >> 1;
    const int warp_n = wid & 1;
    const int bm     = blockIdx.x * 128;

    float acc[2][NI][4];
    #pragma unroll
    for (int mi = 0; mi < 2; ++mi)
        #pragma unroll
        for (int ni = 0; ni < NI; ++ni)
            #pragma unroll
            for (int q = 0; q < 4; ++q) acc[mi][ni][q] = 0.f;

    #pragma unroll
    for (int ph = 0; ph < 2; ++ph) {
        const float* __restrict__ Asrc = ph ? Hin : Agg;
        const float* __restrict__ Wsrc = ph ? Wr : Wl;
        #pragma unroll
        for (int c = 0; c < DI / 32; ++c) {
            const int kl = c * 32;
            #pragma unroll
            for (int i = 0; i < 4; ++i) {
                int flat = tid + i * 256;
                int row = flat >> 3, q = flat & 7;
                int m = bm + row;
                float4 v = make_float4(0.f, 0.f, 0.f, 0.f);
                if (m < NN) v = *(const float4*)(Asrc + (size_t)m * DI + kl + q * 4);
                v.x = to_tf32(v.x); v.y = to_tf32(v.y); v.z = to_tf32(v.z); v.w = to_tf32(v.w);
                *(float4*)(As + row * ST + q * 4) = v;
            }
            #pragma unroll
            for (int i = 0; i < DO / 32; ++i) {
                int flat = tid + i * 256;
                int row = flat >> 3, q = flat & 7;
                float4 v = *(const float4*)(Wsrc + (size_t)row * DI + kl + q * 4);
                v.x = to_tf32(v.x); v.y = to_tf32(v.y); v.z = to_tf32(v.z); v.w = to_tf32(v.w);
                *(float4*)(Ws + row * ST + q * 4) = v;
            }
            __syncthreads();

            #pragma unroll
            for (int kk = 0; kk < 4; ++kk) {
                const int kb = kk * 8;
                uint32_t a[2][4];
                #pragma unroll
                for (int mi = 0; mi < 2; ++mi) {
                    int rb = warp_m * 32 + mi * 16;
                    a[mi][0] = __float_as_uint(As[(rb + g) * ST + kb + tig]);
                    a[mi][1] = __float_as_uint(As[(rb + g + 8) * ST + kb + tig]);
                    a[mi][2] = __float_as_uint(As[(rb + g) * ST + kb + tig + 4]);
                    a[mi][3] = __float_as_uint(As[(rb + g + 8) * ST + kb + tig + 4]);
                }
                #pragma unroll
                for (int ni = 0; ni < NI; ++ni) {
                    int nb = warp_n * WN + ni * 8;
                    uint32_t b0 = __float_as_uint(Ws[(nb + g) * ST + kb + tig]);
                    uint32_t b1 = __float_as_uint(Ws[(nb + g) * ST + kb + tig + 4]);
                    #pragma unroll
                    for (int mi = 0; mi < 2; ++mi)
                        mma_tf32(acc[mi][ni][0], acc[mi][ni][1], acc[mi][ni][2], acc[mi][ni][3],
                                 a[mi][0], a[mi][1], a[mi][2], a[mi][3], b0, b1);
                }
            }
            __syncthreads();
        }
    }

    #pragma unroll
    for (int ni = 0; ni < NI; ++ni) {
        int col = warp_n * WN + ni * 8 + tig * 2;
        float b0 = bl[col], b1 = bl[col + 1];
        #pragma unroll
        for (int mi = 0; mi < 2; ++mi) {
            int r0 = bm + warp_m * 32 + mi * 16 + g;
            if (r0 < NN)
                *(float2*)(out + (size_t)r0 * DO + col) =
                    make_float2(acc[mi][ni][0] + b0, acc[mi][ni][1] + b1);
            int r1 = r0 + 8;
            if (r1 < NN)
                *(float2*)(out + (size_t)r1 * DO + col) =
                    make_float2(acc[mi][ni][2] + b0, acc[mi][ni][3] + b1);
        }
    }
}

// ===================== LayerNorm + ReLU (fp32 in place, + bf16 copy) ==========
__global__ void k_lnrelu(float* __restrict__ h, const float* __restrict__ g,
                         const float* __restrict__ b, __nv_bfloat16* __restrict__ hbf) {
    int n    = (blockIdx.x * blockDim.x + threadIdx.x) >> 5;
    int lane = threadIdx.x & 31;
    if (n >= NN) return;
    float4 v = *(const float4*)(h + (size_t)n * 128 + lane * 4);
    float s = v.x + v.y + v.z + v.w;
    #pragma unroll
    for (int off = 16; off > 0; off >>= 1) s += __shfl_xor_sync(0xFFFFFFFF, s, off);
    float mean = s * (1.0f / 128.0f);
    float dx = v.x - mean, dy = v.y - mean, dz = v.z - mean, dw = v.w - mean;
    float sq = dx * dx + dy * dy + dz * dz + dw * dw;
    #pragma unroll
    for (int off = 16; off > 0; off >>= 1) sq += __shfl_xor_sync(0xFFFFFFFF, sq, off);
    float rs = rsqrtf(sq * (1.0f / 128.0f) + LN_EPS);
    float4 gg = *(const float4*)(g + lane * 4);
    float4 bb = *(const float4*)(b + lane * 4);
    float4 r;
    r.x = fmaxf(dx * rs * gg.x + bb.x, 0.f);
    r.y = fmaxf(dy * rs * gg.y + bb.y, 0.f);
    r.z = fmaxf(dz * rs * gg.z + bb.z, 0.f);
    r.w = fmaxf(dw * rs * gg.w + bb.w, 0.f);
    *(float4*)(h + (size_t)n * 128 + lane * 4) = r;
    __nv_bfloat162 q0 = __floats2bfloat162_rn(r.x, r.y);
    __nv_bfloat162 q1 = __floats2bfloat162_rn(r.z, r.w);
    uint2 pk;
    pk.x = *reinterpret_cast<uint32_t*>(&q0);
    pk.y = *reinterpret_cast<uint32_t*>(&q1);
    *(uint2*)(hbf + (size_t)n * 128 + lane * 4) = pk;
}

// ===================== host =====================
extern "C" void kernel_launch(void* const* d_in, const int* in_sizes, int n_in,
                              void* d_out, int out_size) {
    const float* x   = (const float*)d_in[0];
    const int*   ei  = (const int*)d_in[1];
    const int*   src = ei;
    const int*   dst = ei + EE;

    int *pDeg, *pRow, *pCur, *pCsr;
    float *pInv, *pAgg0, *pA, *pB, *pC;
    __nv_bfloat16* pHbf;
    cudaGetSymbolAddress((void**)&pDeg, g_deg);
    cudaGetSymbolAddress((void**)&pRow, g_rowptr);
    cudaGetSymbolAddress((void**)&pCur, g_cursor);
    cudaGetSymbolAddress((void**)&pCsr, g_csrsrc);
    cudaGetSymbolAddress((void**)&pInv, g_invdeg);
    cudaGetSymbolAddress((void**)&pAgg0, g_agg0);
    cudaGetSymbolAddress((void**)&pA, g_bufA);
    cudaGetSymbolAddress((void**)&pB, g_bufB);
    cudaGetSymbolAddress((void**)&pC, g_bufC);
    cudaGetSymbolAddress((void**)&pHbf, g_hbf);

    const int EB = (EE + 255) / 256;
    const int GW = (NN * 32 + 255) / 256;
    const int DB = (NN + 127) / 128;

    cudaMemsetAsync(pDeg, 0, NN * sizeof(int), 0);
    k_count<<<EB, 256>>>(dst, pDeg);
    k_scan<<<1, 1024>>>(pDeg, pRow, pCur, pInv);
    k_scatter<<<EB, 256>>>(src, dst, pCur, pCsr);

    // shared input aggregation (fp32)
    k_gather64<<<GW, 256>>>(x, pAgg0, pRow, pCsr, pInv);

    for (int t = 0; t < 2; ++t) {
        const int o = 2 + t * 13;
        const float* Wl0 = (const float*)d_in[o + 0];
        const float* bl0 = (const float*)d_in[o + 1];
        const float* Wr0 = (const float*)d_in[o + 2];
        const float* g0  = (const float*)d_in[o + 3];
        const float* b0  = (const float*)d_in[o + 4];
        const float* Wl1 = (const float*)d_in[o + 5];
        const float* bl1 = (const float*)d_in[o + 6];
        const float* Wr1 = (const float*)d_in[o + 7];
        const float* g1  = (const float*)d_in[o + 8];
        const float* b1  = (const float*)d_in[o + 9];
        const float* Wl2 = (const float*)d_in[o + 10];
        const float* bl2 = (const float*)d_in[o + 11];
        const float* Wr2 = (const float*)d_in[o + 12];
        float* outT = (float*)d_out + (size_t)t * NN * 64;

        // layer 0: [agg0 | x] -> h0 ; LN+ReLU writes fp32 + bf16 copy
        k_mma<64, 128><<<DB, 256>>>(pAgg0, x, Wl0, Wr0, bl0, pA);
        k_lnrelu<<<GW, 256>>>(pA, g0, b0, pHbf);
        // layer 1: gather bf16 h0 -> fp32 agg
        k_gather128bf<<<GW, 256>>>(pHbf, pB, pRow, pCsr, pInv);
        k_mma<128, 128><<<DB, 256>>>(pB, pA, Wl1, Wr1, bl1, pC);
        k_lnrelu<<<GW, 256>>>(pC, g1, b1, pHbf);
        // layer 2: gather bf16 h1 -> fp32 agg
        k_gather128bf<<<GW, 256>>>(pHbf, pB, pRow, pCsr, pInv);
        k_mma<128, 64><<<DB, 256>>>(pB, pC, Wl2, Wr2, bl2, outT);
    }
}